// round 12
// baseline (speedup 1.0000x reference)
#include <cuda_runtime.h>
#include <math.h>

#define N_ 307
#define T_ 12
#define B_ 32
#define H_ 64
#define E_ 10
#define NB 307

typedef unsigned long long ull;

constexpr long OFF_A     = 0;
constexpr long OFF_PE    = OFF_A     + 94272;
constexpr long OFF_WG0   = OFF_PE    + 768;
constexpr long OFF_BG0   = OFF_WG0   + 307L*2*65*128;
constexpr long OFF_WU0   = OFF_BG0   + 307L*128;
constexpr long OFF_BU0   = OFF_WU0   + 307L*2*65*64;
constexpr long OFF_WG1   = OFF_BU0   + 307L*64;
constexpr long OFF_BG1   = OFF_WG1   + 307L*2*128*128;
constexpr long OFF_WU1   = OFF_BG1   + 307L*128;
constexpr long OFF_BU1   = OFF_WU1   + 307L*2*128*64;
constexpr long OFF_H     = OFF_BU1   + 307L*64;
constexpr long OFF_HS    = OFF_H     + 32L*307*64;
constexpr long OFF_AX    = OFF_HS    + 32L*12*307*64;
constexpr long OFF_AHS   = OFF_AX    + 307L*384;
constexpr long OFF_SPRH  = OFF_AHS   + 307L*24576;
constexpr long OFF_SPRZH = OFF_SPRH  + 307L*2048;
constexpr long OFF_ZR    = OFF_SPRZH + 307L*2048;
constexpr long OFF_XB11  = OFF_ZR    + 307L*32*128;
constexpr long OFF_K     = OFF_XB11  + 9824L*64;
constexpr long OFF_V     = OFF_K     + 117888L*64;
constexpr long OFF_Q     = OFF_V     + 117888L*64;
constexpr long OFF_OB    = OFF_Q     + 9824L*64;
constexpr long OFF_LN1   = OFF_OB    + 9824L*64;
constexpr long OFF_F1    = OFF_LN1   + 9824L*64;
constexpr long OFF_F2    = OFF_F1    + 9824L*1024;
constexpr long SCRATCH_TOTAL = OFF_F2 + 9824L*64;

__device__ float SCRATCH[SCRATCH_TOTAL];

// ---------------- grid barrier ----------------
__device__ unsigned gCnt[8*32];
__device__ unsigned gMaster;
__device__ unsigned gGen;

__device__ __forceinline__ void gbar(unsigned &gen) {
    __syncthreads();
    if (threadIdx.x == 0) {
        __threadfence();
        int s = blockIdx.x & 7;
        unsigned quota = (s < 3) ? 39u : 38u;   // 307 = 8*38 + 3
        bool released = false;
        if (atomicAdd(&gCnt[s*32], 1) == quota - 1) {
            gCnt[s*32] = 0;
            if (atomicAdd(&gMaster, 1) == 7) {
                gMaster = 0;
                __threadfence();
                atomicAdd(&gGen, 1);
                released = true;
            }
        }
        if (!released) {
            volatile unsigned* gp = &gGen;
            while (*gp == gen) __nanosleep(32);
        }
        __threadfence();
    }
    __syncthreads();
    gen++;
}

// ---------------- setup ----------------
__global__ void kA(const float* __restrict__ emb) {
    int n = blockIdx.x, tid = threadIdx.x;
    __shared__ float sc[N_];
    __shared__ float red[256];
    __shared__ float en[E_];
    if (n == 0) {
        for (int e = tid; e < 768; e += 256) {
            int t = e >> 6, hh = e & 63;
            float j2 = (float)((hh >> 1)*2);
            float ang = (float)t * expf(-(j2/64.f)*9.210340371976184f);
            SCRATCH[OFF_PE + e] = (hh & 1) ? cosf(ang) : sinf(ang);
        }
    }
    if (tid < E_) en[tid] = emb[n*E_ + tid];
    __syncthreads();
    for (int m = tid; m < N_; m += 256) {
        float s = 0.f;
        #pragma unroll
        for (int e = 0; e < E_; e++) s += en[e]*emb[m*E_+e];
        sc[m] = fmaxf(s, 0.f);
    }
    __syncthreads();
    float mx = -1e30f;
    for (int m = tid; m < N_; m += 256) mx = fmaxf(mx, sc[m]);
    red[tid] = mx; __syncthreads();
    for (int s = 128; s > 0; s >>= 1) { if (tid < s) red[tid] = fmaxf(red[tid], red[tid+s]); __syncthreads(); }
    mx = red[0]; __syncthreads();
    float sum = 0.f;
    for (int m = tid; m < N_; m += 256) { float e = expf(sc[m]-mx); sc[m] = e; sum += e; }
    red[tid] = sum; __syncthreads();
    for (int s = 128; s > 0; s >>= 1) { if (tid < s) red[tid] += red[tid+s]; __syncthreads(); }
    float inv = 1.f/red[0];
    __syncthreads();
    for (int m = tid; m < N_; m += 256) SCRATCH[OFF_A + (long)n*N_ + m] = sc[m]*inv;
}

__global__ void kMixAll(const float* __restrict__ gw0, const float* __restrict__ uw0,
                        const float* __restrict__ gw1, const float* __restrict__ uw1,
                        const float* __restrict__ gb0, const float* __restrict__ ub0,
                        const float* __restrict__ gb1, const float* __restrict__ ub1,
                        const float* __restrict__ emb) {
    int n = blockIdx.y;
    __shared__ float en[E_];
    if (threadIdx.x < E_) en[threadIdx.x] = emb[n*E_ + threadIdx.x];
    __syncthreads();
    int bx = blockIdx.x;
    const float* w; long dst; int CO, j0;
    if (bx < 65)       { w = gw0; dst = OFF_WG0; CO = 8320;  j0 = bx*256; }
    else if (bx < 98)  { w = uw0; dst = OFF_WU0; CO = 4160;  j0 = (bx-65)*256; }
    else if (bx < 226) { w = gw1; dst = OFF_WG1; CO = 16384; j0 = (bx-98)*256; }
    else if (bx < 290) { w = uw1; dst = OFF_WU1; CO = 8192;  j0 = (bx-226)*256; }
    else {
        int j = (bx-290)*256 + threadIdx.x;
        if (j < 384) {
            const float* bw; long bdst; int J, jj = j;
            if (jj < 128)      { bw = gb0; bdst = OFF_BG0; J = 128; }
            else if (jj < 192) { bw = ub0; bdst = OFF_BU0; J = 64;  jj -= 128; }
            else if (jj < 320) { bw = gb1; bdst = OFF_BG1; J = 128; jj -= 192; }
            else               { bw = ub1; bdst = OFF_BU1; J = 64;  jj -= 320; }
            float a = 0.f;
            #pragma unroll
            for (int e = 0; e < E_; e++) a += en[e]*bw[e*J + jj];
            SCRATCH[bdst + (long)n*J + jj] = a;
        }
        return;
    }
    int j = j0 + threadIdx.x;
    if (j >= 2*CO) return;
    float a = 0.f;
    #pragma unroll
    for (int e = 0; e < E_; e++) a += en[e]*w[(long)e*2*CO + j];
    int k = j / CO, r = j - k*CO;
    SCRATCH[dst + (long)n*2*CO + (long)r*2 + k] = a;
}

// ---------------- persistent GRU ----------------
template<int MODE>
__device__ __forceinline__ float sprGather(const float* __restrict__ src, int m, int gc) {
    if (MODE == 0) {
        int tt = gc >> 5, b = gc & 31;
        return src[((long)b*T_ + tt)*N_ + m];
    }
    if (MODE == 1) {
        int b = gc >> 6, c = gc & 63;
        return SCRATCH[OFF_H + ((long)b*N_ + m)*H_ + c];
    }
    if (MODE == 2) {
        int b = gc >> 6, c = gc & 63;
        return SCRATCH[OFF_ZR + ((long)m*B_ + b)*128 + c] *
               SCRATCH[OFF_H + ((long)b*N_ + m)*H_ + c];
    }
    int tt = gc >> 11, b = (gc >> 6) & 31, c = gc & 63;
    return SCRATCH[OFF_HS + (((long)b*T_ + tt)*N_ + m)*H_ + c];
}

template<int MODE>
__device__ void dSpread(char* SMB, const float* __restrict__ src, long outOff, int cols) {
    float (*As)[16]  = (float(*)[16])SMB;
    float (*Bs)[132] = (float(*)[132])(SMB + 2048);
    int nColT = cols >> 7;
    int nT = 10 * nColT;
    int tx = threadIdx.x & 15, ty = threadIdx.x >> 4;
    for (int tile = blockIdx.x; tile < nT; tile += NB) {
        int tr = tile / nColT, tc = tile - tr*nColT;
        int row0 = tr*32, col0 = tc*128;
        ull acc[2][4];
        #pragma unroll
        for (int i=0;i<2;i++)
            #pragma unroll
            for (int p=0;p<4;p++) acc[i][p] = 0ull;
        for (int k0 = 0; k0 < N_; k0 += 16) {
            for (int e = threadIdx.x; e < 512; e += 256) {
                int r = e >> 4, c = e & 15, gr = row0 + r, gc = k0 + c;
                As[r][c] = (gr < N_ && gc < N_) ? SCRATCH[OFF_A + (long)gr*N_ + gc] : 0.f;
            }
            for (int e = threadIdx.x; e < 2048; e += 256) {
                int r = e >> 7, c = e & 127, m = k0 + r;
                Bs[r][c] = (m < N_) ? sprGather<MODE>(src, m, col0 + c) : 0.f;
            }
            __syncthreads();
            #pragma unroll
            for (int kk = 0; kk < 16; kk++) {
                ull b0 = *(const ull*)&Bs[kk][2*tx];
                ull b1 = *(const ull*)&Bs[kk][32 + 2*tx];
                ull b2 = *(const ull*)&Bs[kk][64 + 2*tx];
                ull b3 = *(const ull*)&Bs[kk][96 + 2*tx];
                #pragma unroll
                for (int i=0;i<2;i++) {
                    float a = As[ty + 16*i][kk];
                    ull aa;
                    asm("mov.b64 %0, {%1, %1};" : "=l"(aa) : "f"(a));
                    asm("fma.rn.f32x2 %0, %1, %2, %0;" : "+l"(acc[i][0]) : "l"(aa), "l"(b0));
                    asm("fma.rn.f32x2 %0, %1, %2, %0;" : "+l"(acc[i][1]) : "l"(aa), "l"(b1));
                    asm("fma.rn.f32x2 %0, %1, %2, %0;" : "+l"(acc[i][2]) : "l"(aa), "l"(b2));
                    asm("fma.rn.f32x2 %0, %1, %2, %0;" : "+l"(acc[i][3]) : "l"(aa), "l"(b3));
                }
            }
            __syncthreads();
        }
        #pragma unroll
        for (int i=0;i<2;i++) {
            int rr = row0 + ty + 16*i;
            if (rr >= N_) continue;
            #pragma unroll
            for (int p=0;p<4;p++)
                *(float2*)&SCRATCH[outOff + (long)rr*cols + col0 + 32*p + 2*tx] = *(float2*)&acc[i][p];
        }
    }
}

// gate: zr = sigmoid(cat.Wc + spr.Ws + Bg)
// layout: 32 o-lanes x 8 batch-groups; each thread: 4 outputs (o+32q) x 4 batches
template<int C, int L>
__device__ void dGate(char* SMB, const float* __restrict__ src, int t, long wOff, long bOff) {
    int n = blockIdx.x, tid = threadIdx.x;
    float2* cs = (float2*)SMB;
    for (int idx = tid; idx < 32*C; idx += 256) {
        int b = idx / C, c = idx - b*C;
        float cv, sv;
        if (L == 0) {
            if (c == 0) { cv = src[((long)b*T_+t)*N_ + n]; sv = SCRATCH[OFF_AX + (long)n*384 + t*32 + b]; }
            else        { cv = SCRATCH[OFF_H + ((long)b*N_+n)*H_ + (c-1)];
                          sv = SCRATCH[OFF_SPRH + (long)n*2048 + b*64 + (c-1)]; }
        } else {
            if (c < 64) { cv = SCRATCH[OFF_HS + (((long)b*T_+t)*N_+n)*H_ + c];
                          sv = SCRATCH[OFF_AHS + (long)n*24576 + t*2048 + b*64 + c]; }
            else        { cv = SCRATCH[OFF_H + ((long)b*N_+n)*H_ + (c-64)];
                          sv = SCRATCH[OFF_SPRH + (long)n*2048 + b*64 + (c-64)]; }
        }
        cs[idx] = make_float2(cv, sv);
    }
    __syncthreads();
    int o = tid & 31, bg = tid >> 5;   // 8 groups x 4 batches
    ull acc[4][4];                      // [q][bb]
    #pragma unroll
    for (int q=0;q<4;q++)
        #pragma unroll
        for (int bb=0;bb<4;bb++) acc[q][bb]=0ull;
    const float2* Wp = (const float2*)(SCRATCH + wOff + (long)n*(2*C*128));
    const float2* csb = cs + bg*4*C;
    int i = 0;
    for (; i + 2 <= C; i += 2) {
        ull w0[4], w1[4];
        #pragma unroll
        for (int q = 0; q < 4; q++) {
            w0[q] = *(const ull*)(Wp + i*128 + o + 32*q);
            w1[q] = *(const ull*)(Wp + (i+1)*128 + o + 32*q);
        }
        #pragma unroll
        for (int bb = 0; bb < 4; bb++) {
            ull cp0 = *(const ull*)(csb + bb*C + i);
            #pragma unroll
            for (int q = 0; q < 4; q++)
                asm("fma.rn.f32x2 %0, %1, %2, %0;" : "+l"(acc[q][bb]) : "l"(cp0), "l"(w0[q]));
            ull cp1 = *(const ull*)(csb + bb*C + i + 1);
            #pragma unroll
            for (int q = 0; q < 4; q++)
                asm("fma.rn.f32x2 %0, %1, %2, %0;" : "+l"(acc[q][bb]) : "l"(cp1), "l"(w1[q]));
        }
    }
    for (; i < C; i++) {
        ull w0[4];
        #pragma unroll
        for (int q = 0; q < 4; q++) w0[q] = *(const ull*)(Wp + i*128 + o + 32*q);
        #pragma unroll
        for (int bb = 0; bb < 4; bb++) {
            ull cp0 = *(const ull*)(csb + bb*C + i);
            #pragma unroll
            for (int q = 0; q < 4; q++)
                asm("fma.rn.f32x2 %0, %1, %2, %0;" : "+l"(acc[q][bb]) : "l"(cp0), "l"(w0[q]));
        }
    }
    #pragma unroll
    for (int q = 0; q < 4; q++) {
        float biasq = SCRATCH[bOff + (long)n*128 + o + 32*q];
        #pragma unroll
        for (int bb = 0; bb < 4; bb++) {
            float2 a = *(float2*)&acc[q][bb];
            long zi = OFF_ZR + ((long)n*32 + bg*4+bb)*128 + o + 32*q;
            SCRATCH[zi] = 1.f/(1.f + expf(-(a.x + a.y + biasq)));
        }
    }
}

// update: hc = tanh(...); h = r*h + (1-r)*hc
// layout: 16 o-lanes x 16 batch-groups; each thread: 4 outputs (o+16q) x 2 batches
template<int C, int L>
__device__ void dUpd(char* SMB, const float* __restrict__ src, int t, long wOff, long bOff, int writeHS) {
    int n = blockIdx.x, tid = threadIdx.x;
    float2* cs = (float2*)SMB;
    for (int idx = tid; idx < 32*C; idx += 256) {
        int b = idx / C, c = idx - b*C;
        float cv, sv;
        if (L == 0) {
            if (c == 0) { cv = src[((long)b*T_+t)*N_ + n]; sv = SCRATCH[OFF_AX + (long)n*384 + t*32 + b]; }
            else {
                int j = c-1;
                cv = SCRATCH[OFF_ZR + ((long)n*32+b)*128 + j] * SCRATCH[OFF_H + ((long)b*N_+n)*H_ + j];
                sv = SCRATCH[OFF_SPRZH + (long)n*2048 + b*64 + j];
            }
        } else {
            if (c < 64) { cv = SCRATCH[OFF_HS + (((long)b*T_+t)*N_+n)*H_ + c];
                          sv = SCRATCH[OFF_AHS + (long)n*24576 + t*2048 + b*64 + c]; }
            else {
                int j = c-64;
                cv = SCRATCH[OFF_ZR + ((long)n*32+b)*128 + j] * SCRATCH[OFF_H + ((long)b*N_+n)*H_ + j];
                sv = SCRATCH[OFF_SPRZH + (long)n*2048 + b*64 + j];
            }
        }
        cs[idx] = make_float2(cv, sv);
    }
    __syncthreads();
    int o = tid & 15, bg = tid >> 4;   // 16 groups x 2 batches
    ull acc[4][2];                      // [q][bb]
    #pragma unroll
    for (int q=0;q<4;q++)
        #pragma unroll
        for (int bb=0;bb<2;bb++) acc[q][bb]=0ull;
    const float2* Wp = (const float2*)(SCRATCH + wOff + (long)n*(2*C*64));
    const float2* csb = cs + bg*2*C;
    int i = 0;
    for (; i + 2 <= C; i += 2) {
        ull w0[4], w1[4];
        #pragma unroll
        for (int q = 0; q < 4; q++) {
            w0[q] = *(const ull*)(Wp + i*64 + o + 16*q);
            w1[q] = *(const ull*)(Wp + (i+1)*64 + o + 16*q);
        }
        #pragma unroll
        for (int bb = 0; bb < 2; bb++) {
            ull cp0 = *(const ull*)(csb + bb*C + i);
            #pragma unroll
            for (int q = 0; q < 4; q++)
                asm("fma.rn.f32x2 %0, %1, %2, %0;" : "+l"(acc[q][bb]) : "l"(cp0), "l"(w0[q]));
            ull cp1 = *(const ull*)(csb + bb*C + i + 1);
            #pragma unroll
            for (int q = 0; q < 4; q++)
                asm("fma.rn.f32x2 %0, %1, %2, %0;" : "+l"(acc[q][bb]) : "l"(cp1), "l"(w1[q]));
        }
    }
    for (; i < C; i++) {
        ull w0[4];
        #pragma unroll
        for (int q = 0; q < 4; q++) w0[q] = *(const ull*)(Wp + i*64 + o + 16*q);
        #pragma unroll
        for (int bb = 0; bb < 2; bb++) {
            ull cp0 = *(const ull*)(csb + bb*C + i);
            #pragma unroll
            for (int q = 0; q < 4; q++)
                asm("fma.rn.f32x2 %0, %1, %2, %0;" : "+l"(acc[q][bb]) : "l"(cp0), "l"(w0[q]));
        }
    }
    #pragma unroll
    for (int q = 0; q < 4; q++) {
        int oo = o + 16*q;
        float biasq = SCRATCH[bOff + (long)n*64 + oo];
        #pragma unroll
        for (int bb = 0; bb < 2; bb++) {
            int b = bg*2 + bb;
            float2 a = *(float2*)&acc[q][bb];
            float hc = tanhf(a.x + a.y + biasq);
            float r  = SCRATCH[OFF_ZR + ((long)n*32 + b)*128 + 64 + oo];
            long hidx = OFF_H + ((long)b*N_ + n)*H_ + oo;
            float hn = r*SCRATCH[hidx] + (1.f - r)*hc;
            SCRATCH[hidx] = hn;
            if (writeHS) SCRATCH[OFF_HS + (((long)b*T_ + t)*N_ + n)*H_ + oo] = hn;
        }
    }
}

__device__ __forceinline__ void dZeroH() {
    for (long i = (long)blockIdx.x*256 + threadIdx.x; i < 32L*307*64; i += (long)NB*256)
        SCRATCH[OFF_H + i] = 0.f;
}

__global__ void __launch_bounds__(256, 3) kGRU(const float* __restrict__ src) {
    __shared__ __align__(16) char SMB[33280];
    unsigned gen = 0;
    if (threadIdx.x == 0) gen = atomicAdd(&gGen, 0);

    dSpread<0>(SMB, src, OFF_AX, 384);
    dZeroH();
    gbar(gen);

    for (int t = 0; t < T_; t++) {       // layer 0
        dSpread<1>(SMB, src, OFF_SPRH, 2048);   gbar(gen);
        dGate<65,0>(SMB, src, t, OFF_WG0, OFF_BG0);  gbar(gen);
        dSpread<2>(SMB, src, OFF_SPRZH, 2048);  gbar(gen);
        dUpd<65,0>(SMB, src, t, OFF_WU0, OFF_BU0, 1); gbar(gen);
    }

    dSpread<3>(SMB, src, OFF_AHS, 24576);
    dZeroH();
    gbar(gen);

    for (int t = 0; t < T_; t++) {       // layer 1
        dSpread<1>(SMB, src, OFF_SPRH, 2048);   gbar(gen);
        dGate<128,1>(SMB, src, t, OFF_WG1, OFF_BG1); gbar(gen);
        dSpread<2>(SMB, src, OFF_SPRZH, 2048);  gbar(gen);
        dUpd<128,1>(SMB, src, t, OFF_WU1, OFF_BU1, 0); gbar(gen);
    }
}

// ---------------- transformer branch ----------------
__global__ void __launch_bounds__(256) kKV(const float* __restrict__ src,
        const float* __restrict__ mw, const float* __restrict__ mb,
        const float* __restrict__ wk, const float* __restrict__ bk,
        const float* __restrict__ wv, const float* __restrict__ bv) {
    __shared__ float xbT[64][64];
    __shared__ float wks[64][64];
    __shared__ float wvs[64][64];
    int tid = threadIdx.x, blk = blockIdx.x;

    if (tid < 64) {
        int row = blk*64 + tid;
        int t = row % 12, s = row / 12;
        int n = s % N_, b = s / N_;
        wks[0][tid] = src[((long)b*T_ + t)*N_ + n];
    }
    __syncthreads();
    for (int e = tid; e < 4096; e += 256) {
        int r = e >> 6, h = e & 63;
        int t = (blk*64 + r) % 12;
        xbT[h][r] = wks[0][r]*mw[h] + mb[h] + SCRATCH[OFF_PE + t*64 + h];
    }
    __syncthreads();
    for (int e = tid; e < 4096; e += 256) {
        wks[e >> 6][e & 63] = wk[e];
        wvs[e >> 6][e & 63] = wv[e];
    }
    __syncthreads();

    int col = tid & 63, rg = tid >> 6;
    ull accK[8], accV[8];
    #pragma unroll
    for (int i=0;i<8;i++){accK[i]=0ull;accV[i]=0ull;}
    #pragma unroll 4
    for (int kk = 0; kk < 64; kk++) {
        float a = wks[kk][col], b = wvs[kk][col];
        ull w1, w2;
        asm("mov.b64 %0, {%1, %1};" : "=l"(w1) : "f"(a));
        asm("mov.b64 %0, {%1, %1};" : "=l"(w2) : "f"(b));
        const ull* xp = (const ull*)&xbT[kk][rg*16];
        #pragma unroll
        for (int i=0;i<8;i++) {
            ull x = xp[i];
            asm("fma.rn.f32x2 %0, %1, %2, %0;" : "+l"(accK[i]) : "l"(x), "l"(w1));
            asm("fma.rn.f32x2 %0, %1, %2, %0;" : "+l"(accV[i]) : "l"(x), "l"(w2));
        }
    }
    float bkc = bk[col], bvc = bv[col];
    #pragma unroll
    for (int i=0;i<8;i++) {
        float2 k2 = *(float2*)&accK[i];
        float2 v2 = *(float2*)&accV[i];
        long r0 = ((long)blk*64 + rg*16 + 2*i)*64 + col;
        SCRATCH[OFF_K + r0]      = k2.x + bkc;
        SCRATCH[OFF_K + r0 + 64] = k2.y + bkc;
        SCRATCH[OFF_V + r0]      = v2.x + bvc;
        SCRATCH[OFF_V + r0 + 64] = v2.y + bvc;
    }
    for (int e = tid; e < 4096; e += 256) {
        int r = e >> 6, h = e & 63;
        int row = blk*64 + r;
        if (row % 12 == 11)
            SCRATCH[OFF_XB11 + (long)(row/12)*64 + h] = xbT[h][r];
    }
}

template<int NT>
__global__ void __launch_bounds__(256) kMM(long aOff, int lda,
        const float* __restrict__ Bx, int ldb,
        long cOff, int ldc, const float* __restrict__ bias,
        long resOff, int ldres, int hasRes,
        int M, int K, int Nc, int relu) {
    const int P = NT/32;
    const float* A = SCRATCH + aOff;
    float* Cm = SCRATCH + cOff;
    __shared__ float As[64][16];
    __shared__ float Bs[16][NT+2];
    int tx = threadIdx.x & 15, ty = threadIdx.x >> 4;
    int row0 = blockIdx.y*64, col0 = blockIdx.x*NT;
    ull acc[4][P];
    #pragma unroll
    for (int i=0;i<4;i++)
        #pragma unroll
        for (int p=0;p<P;p++) acc[i][p] = 0ull;
    for (int k0 = 0; k0 < K; k0 += 16) {
        for (int e = threadIdx.x; e < 64*16; e += 256) {
            int r = e >> 4, c = e & 15, gr = row0 + r, gc = k0 + c;
            As[r][c] = (gr < M && gc < K) ? A[(long)gr*lda + gc] : 0.f;
        }
        for (int e = threadIdx.x; e < 16*NT; e += 256) {
            int r = e / NT, c = e - (e/NT)*NT;
            int gr = k0 + r, gc = col0 + c;
            Bs[r][c] = (gr < K && gc < Nc) ? Bx[(long)gr*ldb + gc] : 0.f;
        }
        __syncthreads();
        #pragma unroll
        for (int kk = 0; kk < 16; kk++) {
            ull bv[P];
            #pragma unroll
            for (int p=0;p<P;p++) bv[p] = *(const ull*)&Bs[kk][32*p + 2*tx];
            #pragma unroll
            for (int i=0;i<4;i++) {
                float a = As[ty + 16*i][kk];
                ull aa;
                asm("mov.b64 %0, {%1, %1};" : "=l"(aa) : "f"(a));
                #pragma unroll
                for (int p=0;p<P;p++)
                    asm("fma.rn.f32x2 %0, %1, %2, %0;" : "+l"(acc[i][p]) : "l"(aa), "l"(bv[p]));
            }
        }
        __syncthreads();
    }
    #pragma unroll
    for (int i=0;i<4;i++) {
        int rr = row0 + ty + 16*i;
        if (rr >= M) continue;
        #pragma unroll
        for (int p=0;p<P;p++) {
            float2 v = *(float2*)&acc[i][p];
            int cc = col0 + 32*p + 2*tx;
            #pragma unroll
            for (int q=0;q<2;q++) {
                int c2 = cc + q;
                if (c2 >= Nc) continue;
                float val = q ? v.y : v.x;
                if (bias)   val += bias[c2];
                if (hasRes) val += SCRATCH[resOff + (long)rr*ldres + c2];
                if (relu)   val = fmaxf(val, 0.f);
                Cm[(long)rr*ldc + c2] = val;
            }
        }
    }
}

__global__ void kAttn() {
    int s = blockIdx.x, tid = threadIdx.x;
    int w = tid >> 5, lane = tid & 31;
    __shared__ float qs[64];
    __shared__ float att[4][12];
    if (tid < 64) qs[tid] = SCRATCH[OFF_Q + (long)s*64 + tid];
    __syncthreads();
    if (lane < 12) {
        float sc = 0.f;
        #pragma unroll
        for (int d = 0; d < 16; d++)
            sc += qs[w*16+d] * SCRATCH[OFF_K + (long)s*768 + lane*64 + w*16 + d];
        att[w][lane] = sc * 0.25f;
    }
    __syncwarp();
    float loc[12], mx = -1e30f, sum = 0.f;
    #pragma unroll
    for (int t = 0; t < 12; t++) { loc[t] = att[w][t]; mx = fmaxf(mx, loc[t]); }
    #pragma unroll
    for (int t = 0; t < 12; t++) { loc[t] = expf(loc[t]-mx); sum += loc[t]; }
    float inv = 1.f/sum;
    __syncwarp();
    if (lane < 16) {
        float acc = 0.f;
        #pragma unroll
        for (int t = 0; t < 12; t++)
            acc += loc[t]*inv * SCRATCH[OFF_V + (long)s*768 + t*64 + w*16 + lane];
        SCRATCH[OFF_OB + (long)s*64 + w*16 + lane] = acc;
    }
}

__global__ void kLN(long inOff, long outOff, const float* __restrict__ g, const float* __restrict__ b) {
    int row = blockIdx.x, tid = threadIdx.x;
    __shared__ float red[64];
    float v = SCRATCH[inOff + (long)row*64 + tid];
    red[tid] = v; __syncthreads();
    for (int s = 32; s > 0; s >>= 1) { if (tid < s) red[tid] += red[tid+s]; __syncthreads(); }
    float m = red[0]/64.f; __syncthreads();
    float d = v - m;
    red[tid] = d*d; __syncthreads();
    for (int s = 32; s > 0; s >>= 1) { if (tid < s) red[tid] += red[tid+s]; __syncthreads(); }
    float var = red[0]/64.f;
    SCRATCH[outOff + (long)row*64 + tid] = d*rsqrtf(var + 1e-5f)*g[tid] + b[tid];
}

__global__ void kOut(float* __restrict__ out, const float* __restrict__ ws, const float* __restrict__ wt,
                     const float* __restrict__ cw, const float* __restrict__ cb) {
    int s = blockIdx.x, tid = threadIdx.x;
    int n = s % N_, b = s / N_;
    __shared__ float comb[64];
    comb[tid] = SCRATCH[OFF_H + (long)s*64 + tid]*ws[n*64+tid]
              + SCRATCH[OFF_OB + (long)s*64 + tid]*wt[n*64+tid];
    __syncthreads();
    if (tid < 12) {
        float acc = cb[tid];
        #pragma unroll
        for (int h = 0; h < 64; h++) acc += comb[h]*cw[tid*64+h];
        out[((long)b*12 + tid)*N_ + n] = acc;
    }
}

extern "C" void kernel_launch(void* const* d_in, const int* in_sizes, int n_in,
                              void* d_out, int out_size) {
    const float* source  = (const float*)d_in[0];
    const float* emb     = (const float*)d_in[1];
    const float* gate_w0 = (const float*)d_in[2];
    const float* gate_b0 = (const float*)d_in[3];
    const float* upd_w0  = (const float*)d_in[4];
    const float* upd_b0  = (const float*)d_in[5];
    const float* gate_w1 = (const float*)d_in[6];
    const float* gate_b1 = (const float*)d_in[7];
    const float* upd_w1  = (const float*)d_in[8];
    const float* upd_b1  = (const float*)d_in[9];
    const float* mlp_w   = (const float*)d_in[10];
    const float* mlp_b   = (const float*)d_in[11];
    const float* wq = (const float*)d_in[12];  const float* bq = (const float*)d_in[13];
    const float* wk = (const float*)d_in[14];  const float* bk = (const float*)d_in[15];
    const float* wv = (const float*)d_in[16];  const float* bv = (const float*)d_in[17];
    const float* wo = (const float*)d_in[18];  const float* bo = (const float*)d_in[19];
    const float* fw1 = (const float*)d_in[20]; const float* fb1 = (const float*)d_in[21];
    const float* fw2 = (const float*)d_in[22]; const float* fb2 = (const float*)d_in[23];
    const float* l1g = (const float*)d_in[24]; const float* l1b = (const float*)d_in[25];
    const float* l2g = (const float*)d_in[26]; const float* l2b = (const float*)d_in[27];
    const float* ws  = (const float*)d_in[28]; const float* wt  = (const float*)d_in[29];
    const float* cw  = (const float*)d_in[30]; const float* cb  = (const float*)d_in[31];
    float* out = (float*)d_out;

    kA<<<N_, 256>>>(emb);
    kMixAll<<<dim3(292, N_), 256>>>(gate_w0, upd_w0, gate_w1, upd_w1,
                                    gate_b0, upd_b0, gate_b1, upd_b1, emb);
    kKV<<<1842, 256>>>(source, mlp_w, mlp_b, wk, bk, wv, bv);

    kGRU<<<NB, 256>>>(source);

    kMM<64><<<dim3(1,154),256>>>(OFF_XB11,64, wq,64, OFF_Q,64, bq, 0,0,0, 9824,64,64,0);
    kAttn<<<9824,128>>>();
    kMM<64><<<dim3(1,154),256>>>(OFF_OB,64, wo,64, OFF_Q,64, bo, OFF_XB11,64,1, 9824,64,64,0);
    kLN<<<9824,64>>>(OFF_Q, OFF_LN1, l1g, l1b);
    kMM<128><<<dim3(8,154),256>>>(OFF_LN1,64, fw1,1024, OFF_F1,1024, fb1, 0,0,0, 9824,64,1024,1);
    kMM<64><<<dim3(1,154),256>>>(OFF_F1,1024, fw2,64, OFF_F2,64, fb2, OFF_LN1,64,1, 9824,1024,64,0);
    kLN<<<9824,64>>>(OFF_F2, OFF_OB, l2g, l2b);

    kOut<<<9824,64>>>(out, ws, wt, cw, cb);
}

// round 15
// speedup vs baseline: 1.6120x; 1.6120x over previous
#include <cuda_runtime.h>
#include <math.h>

#define N_ 307
#define T_ 12
#define B_ 32
#define H_ 64
#define E_ 10
#define NB 307

typedef unsigned long long ull;

constexpr long HSZ = 32L*307*64;
constexpr long OFF_A     = 0;
constexpr long OFF_PE    = OFF_A     + 94272;
constexpr long OFF_WG0   = OFF_PE    + 768;
constexpr long OFF_BG0   = OFF_WG0   + 307L*2*65*128;
constexpr long OFF_WU0   = OFF_BG0   + 307L*128;
constexpr long OFF_BU0   = OFF_WU0   + 307L*2*65*64;
constexpr long OFF_WG1   = OFF_BU0   + 307L*64;
constexpr long OFF_BG1   = OFF_WG1   + 307L*2*128*128;
constexpr long OFF_WU1   = OFF_BG1   + 307L*128;
constexpr long OFF_BU1   = OFF_WU1   + 307L*2*128*64;
constexpr long OFF_H     = OFF_BU1   + 307L*64;     // two h buffers
constexpr long OFF_HS    = OFF_H     + 2*HSZ;
constexpr long OFF_AX    = OFF_HS    + 32L*12*307*64;
constexpr long OFF_AHS   = OFF_AX    + 307L*384;
constexpr long OFF_SPRH  = OFF_AHS   + 307L*24576;
constexpr long OFF_SPRZH = OFF_SPRH  + 307L*2048;
constexpr long OFF_ZR    = OFF_SPRZH + 307L*2048;
constexpr long OFF_XB11  = OFF_ZR    + 307L*32*128;
constexpr long OFF_K     = OFF_XB11  + 9824L*64;
constexpr long OFF_V     = OFF_K     + 117888L*64;
constexpr long OFF_Q     = OFF_V     + 117888L*64;
constexpr long OFF_OB    = OFF_Q     + 9824L*64;
constexpr long OFF_LN1   = OFF_OB    + 9824L*64;
constexpr long OFF_F1    = OFF_LN1   + 9824L*64;
constexpr long OFF_F2    = OFF_F1    + 9824L*1024;
constexpr long SCRATCH_TOTAL = OFF_F2 + 9824L*64;

__device__ float SCRATCH[SCRATCH_TOTAL];

// ---------------- grid barrier + fine-grained row-group flags ----------------
__device__ unsigned gCnt[8*32];
__device__ unsigned gMaster;
__device__ unsigned gGen;
__device__ unsigned sF1[10*32];   // spr1 tile-completion counters per row-group
__device__ unsigned sF2[10*32];   // spr2 tile-completion counters

__device__ __forceinline__ void gbar(unsigned &gen) {
    __syncthreads();
    if (threadIdx.x == 0) {
        __threadfence();
        int s = blockIdx.x & 7;
        unsigned quota = (s < 3) ? 39u : 38u;   // 307 = 8*38 + 3
        bool released = false;
        if (atomicAdd(&gCnt[s*32], 1) == quota - 1) {
            gCnt[s*32] = 0;
            if (atomicAdd(&gMaster, 1) == 7) {
                gMaster = 0;
                __threadfence();
                atomicAdd(&gGen, 1);
                released = true;
            }
        }
        if (!released) {
            volatile unsigned* gp = &gGen;
            while (*gp == gen) __nanosleep(32);
        }
        __threadfence();
    }
    __syncthreads();
    gen++;
}

// wait until row-group rg has 16*ep tiles complete (counter-base form, replay-safe)
__device__ __forceinline__ void finewait(unsigned* flag, unsigned base, int ep) {
    if (threadIdx.x == 0) {
        unsigned target = 16u*(unsigned)ep;
        volatile unsigned* f = flag;
        while (*f - base < target) __nanosleep(32);
        __threadfence();
    }
    __syncthreads();
}

// ---------------- setup ----------------
__global__ void kA(const float* __restrict__ emb) {
    int n = blockIdx.x, tid = threadIdx.x;
    __shared__ float sc[N_];
    __shared__ float red[256];
    __shared__ float en[E_];
    if (n == 0) {
        for (int e = tid; e < 768; e += 256) {
            int t = e >> 6, hh = e & 63;
            float j2 = (float)((hh >> 1)*2);
            float ang = (float)t * expf(-(j2/64.f)*9.210340371976184f);
            SCRATCH[OFF_PE + e] = (hh & 1) ? cosf(ang) : sinf(ang);
        }
    }
    if (tid < E_) en[tid] = emb[n*E_ + tid];
    __syncthreads();
    for (int m = tid; m < N_; m += 256) {
        float s = 0.f;
        #pragma unroll
        for (int e = 0; e < E_; e++) s += en[e]*emb[m*E_+e];
        sc[m] = fmaxf(s, 0.f);
    }
    __syncthreads();
    float mx = -1e30f;
    for (int m = tid; m < N_; m += 256) mx = fmaxf(mx, sc[m]);
    red[tid] = mx; __syncthreads();
    for (int s = 128; s > 0; s >>= 1) { if (tid < s) red[tid] = fmaxf(red[tid], red[tid+s]); __syncthreads(); }
    mx = red[0]; __syncthreads();
    float sum = 0.f;
    for (int m = tid; m < N_; m += 256) { float e = expf(sc[m]-mx); sc[m] = e; sum += e; }
    red[tid] = sum; __syncthreads();
    for (int s = 128; s > 0; s >>= 1) { if (tid < s) red[tid] += red[tid+s]; __syncthreads(); }
    float inv = 1.f/red[0];
    __syncthreads();
    for (int m = tid; m < N_; m += 256) SCRATCH[OFF_A + (long)n*N_ + m] = sc[m]*inv;
}

__global__ void kMixAll(const float* __restrict__ gw0, const float* __restrict__ uw0,
                        const float* __restrict__ gw1, const float* __restrict__ uw1,
                        const float* __restrict__ gb0, const float* __restrict__ ub0,
                        const float* __restrict__ gb1, const float* __restrict__ ub1,
                        const float* __restrict__ emb) {
    int n = blockIdx.y;
    __shared__ float en[E_];
    if (threadIdx.x < E_) en[threadIdx.x] = emb[n*E_ + threadIdx.x];
    __syncthreads();
    int bx = blockIdx.x;
    const float* w; long dst; int CO, j0;
    if (bx < 65)       { w = gw0; dst = OFF_WG0; CO = 8320;  j0 = bx*256; }
    else if (bx < 98)  { w = uw0; dst = OFF_WU0; CO = 4160;  j0 = (bx-65)*256; }
    else if (bx < 226) { w = gw1; dst = OFF_WG1; CO = 16384; j0 = (bx-98)*256; }
    else if (bx < 290) { w = uw1; dst = OFF_WU1; CO = 8192;  j0 = (bx-226)*256; }
    else {
        int j = (bx-290)*256 + threadIdx.x;
        if (j < 384) {
            const float* bw; long bdst; int J, jj = j;
            if (jj < 128)      { bw = gb0; bdst = OFF_BG0; J = 128; }
            else if (jj < 192) { bw = ub0; bdst = OFF_BU0; J = 64;  jj -= 128; }
            else if (jj < 320) { bw = gb1; bdst = OFF_BG1; J = 128; jj -= 192; }
            else               { bw = ub1; bdst = OFF_BU1; J = 64;  jj -= 320; }
            float a = 0.f;
            #pragma unroll
            for (int e = 0; e < E_; e++) a += en[e]*bw[e*J + jj];
            SCRATCH[bdst + (long)n*J + jj] = a;
        }
        return;
    }
    int j = j0 + threadIdx.x;
    if (j >= 2*CO) return;
    float a = 0.f;
    #pragma unroll
    for (int e = 0; e < E_; e++) a += en[e]*w[(long)e*2*CO + j];
    int k = j / CO, r = j - k*CO;
    SCRATCH[dst + (long)n*2*CO + (long)r*2 + k] = a;
}

// ---------------- persistent GRU ----------------
// modes: 0 = x (all t), 1 = h, 2 = z*h, 3 = hs (all t)
template<int MODE>
__device__ __forceinline__ float sprGather(const float* __restrict__ src, long hOff, int m, int gc) {
    if (MODE == 0) {
        int tt = gc >> 5, b = gc & 31;
        return src[((long)b*T_ + tt)*N_ + m];
    }
    if (MODE == 1) {
        int b = gc >> 6, c = gc & 63;
        return SCRATCH[hOff + ((long)b*N_ + m)*H_ + c];
    }
    if (MODE == 2) {
        int b = gc >> 6, c = gc & 63;
        return SCRATCH[OFF_ZR + ((long)m*B_ + b)*128 + c] *
               SCRATCH[hOff + ((long)b*N_ + m)*H_ + c];
    }
    int tt = gc >> 11, b = (gc >> 6) & 31, c = gc & 63;
    return SCRATCH[OFF_HS + (((long)b*T_ + tt)*N_ + m)*H_ + c];
}

// full spread; if flag != nullptr, release-increment flag[rowgroup] per finished tile
template<int MODE>
__device__ void dSpread(char* SMB, const float* __restrict__ src, long hOff,
                        long outOff, int cols, unsigned* flag) {
    float (*As)[16]  = (float(*)[16])SMB;
    float (*Bs)[132] = (float(*)[132])(SMB + 2048);
    int nColT = cols >> 7;
    int nT = 10 * nColT;
    int tx = threadIdx.x & 15, ty = threadIdx.x >> 4;
    for (int tile = blockIdx.x; tile < nT; tile += NB) {
        int tr = tile / nColT, tc = tile - tr*nColT;
        int row0 = tr*32, col0 = tc*128;
        ull acc[2][4];
        #pragma unroll
        for (int i=0;i<2;i++)
            #pragma unroll
            for (int p=0;p<4;p++) acc[i][p] = 0ull;
        for (int k0 = 0; k0 < N_; k0 += 16) {
            for (int e = threadIdx.x; e < 512; e += 256) {
                int r = e >> 4, c = e & 15, gr = row0 + r, gc = k0 + c;
                As[r][c] = (gr < N_ && gc < N_) ? SCRATCH[OFF_A + (long)gr*N_ + gc] : 0.f;
            }
            for (int e = threadIdx.x; e < 2048; e += 256) {
                int r = e >> 7, c = e & 127, m = k0 + r;
                Bs[r][c] = (m < N_) ? sprGather<MODE>(src, hOff, m, col0 + c) : 0.f;
            }
            __syncthreads();
            #pragma unroll
            for (int kk = 0; kk < 16; kk++) {
                ull b0 = *(const ull*)&Bs[kk][2*tx];
                ull b1 = *(const ull*)&Bs[kk][32 + 2*tx];
                ull b2 = *(const ull*)&Bs[kk][64 + 2*tx];
                ull b3 = *(const ull*)&Bs[kk][96 + 2*tx];
                #pragma unroll
                for (int i=0;i<2;i++) {
                    float a = As[ty + 16*i][kk];
                    ull aa;
                    asm("mov.b64 %0, {%1, %1};" : "=l"(aa) : "f"(a));
                    asm("fma.rn.f32x2 %0, %1, %2, %0;" : "+l"(acc[i][0]) : "l"(aa), "l"(b0));
                    asm("fma.rn.f32x2 %0, %1, %2, %0;" : "+l"(acc[i][1]) : "l"(aa), "l"(b1));
                    asm("fma.rn.f32x2 %0, %1, %2, %0;" : "+l"(acc[i][2]) : "l"(aa), "l"(b2));
                    asm("fma.rn.f32x2 %0, %1, %2, %0;" : "+l"(acc[i][3]) : "l"(aa), "l"(b3));
                }
            }
            __syncthreads();
        }
        #pragma unroll
        for (int i=0;i<2;i++) {
            int rr = row0 + ty + 16*i;
            if (rr >= N_) continue;
            #pragma unroll
            for (int p=0;p<4;p++)
                *(float2*)&SCRATCH[outOff + (long)rr*cols + col0 + 32*p + 2*tx] = *(float2*)&acc[i][p];
        }
        if (flag) {
            __threadfence();
            __syncthreads();
            if (threadIdx.x == 0) atomicAdd(&flag[tr*32], 1);
        }
    }
}

// gate: zr = sigmoid(cat.Wc + spr.Ws + Bg)  (R9 chunk-4 prefetch layout)
template<int C, int L>
__device__ void dGate(char* SMB, const float* __restrict__ src, int t, long wOff, long bOff,
                      long hOff, unsigned base, int ep) {
    int n = blockIdx.x, tid = threadIdx.x;
    finewait(&sF1[(n >> 5)*32], base, ep);
    float2* cs = (float2*)SMB;
    for (int idx = tid; idx < 32*C; idx += 256) {
        int b = idx / C, c = idx - b*C;
        float cv, sv;
        if (L == 0) {
            if (c == 0) { cv = src[((long)b*T_+t)*N_ + n]; sv = SCRATCH[OFF_AX + (long)n*384 + t*32 + b]; }
            else        { cv = SCRATCH[hOff + ((long)b*N_+n)*H_ + (c-1)];
                          sv = SCRATCH[OFF_SPRH + (long)n*2048 + b*64 + (c-1)]; }
        } else {
            if (c < 64) { cv = SCRATCH[OFF_HS + (((long)b*T_+t)*N_+n)*H_ + c];
                          sv = SCRATCH[OFF_AHS + (long)n*24576 + t*2048 + b*64 + c]; }
            else        { cv = SCRATCH[hOff + ((long)b*N_+n)*H_ + (c-64)];
                          sv = SCRATCH[OFF_SPRH + (long)n*2048 + b*64 + (c-64)]; }
        }
        cs[idx] = make_float2(cv, sv);
    }
    __syncthreads();
    int o = tid & 63, bg = tid >> 6;
    ull acc0[8], acc1[8];
    #pragma unroll
    for (int i=0;i<8;i++){acc0[i]=0ull;acc1[i]=0ull;}
    const float2* Wp = (const float2*)(SCRATCH + wOff + (long)n*(2*C*128));
    const float2* csb = cs + bg*8*C;
    int i = 0;
    for (; i + 4 <= C; i += 4) {
        ull wa[4], wb[4];
        #pragma unroll
        for (int j = 0; j < 4; j++) {
            wa[j] = *(const ull*)(Wp + (i+j)*128 + o);
            wb[j] = *(const ull*)(Wp + (i+j)*128 + o + 64);
        }
        #pragma unroll
        for (int j = 0; j < 4; j++) {
            #pragma unroll
            for (int bb = 0; bb < 8; bb++) {
                ull cp = *(const ull*)(csb + bb*C + i + j);
                asm("fma.rn.f32x2 %0, %1, %2, %0;" : "+l"(acc0[bb]) : "l"(cp), "l"(wa[j]));
                asm("fma.rn.f32x2 %0, %1, %2, %0;" : "+l"(acc1[bb]) : "l"(cp), "l"(wb[j]));
            }
        }
    }
    for (; i < C; i++) {
        ull wa = *(const ull*)(Wp + i*128 + o);
        ull wb = *(const ull*)(Wp + i*128 + o + 64);
        #pragma unroll
        for (int bb = 0; bb < 8; bb++) {
            ull cp = *(const ull*)(csb + bb*C + i);
            asm("fma.rn.f32x2 %0, %1, %2, %0;" : "+l"(acc0[bb]) : "l"(cp), "l"(wa));
            asm("fma.rn.f32x2 %0, %1, %2, %0;" : "+l"(acc1[bb]) : "l"(cp), "l"(wb));
        }
    }
    float bias0 = SCRATCH[bOff + (long)n*128 + o];
    float bias1 = SCRATCH[bOff + (long)n*128 + o + 64];
    #pragma unroll
    for (int bb = 0; bb < 8; bb++) {
        float2 a0 = *(float2*)&acc0[bb];
        float2 a1 = *(float2*)&acc1[bb];
        long zi = OFF_ZR + ((long)n*32 + bg*8+bb)*128 + o;
        SCRATCH[zi]      = 1.f/(1.f + expf(-(a0.x + a0.y + bias0)));
        SCRATCH[zi + 64] = 1.f/(1.f + expf(-(a1.x + a1.y + bias1)));
    }
}

// update (R9 chunk-8 prefetch layout), h double-buffered
template<int C, int L>
__device__ void dUpd(char* SMB, const float* __restrict__ src, int t, long wOff, long bOff,
                     long hRead, long hWrite, int writeHS, unsigned base, int ep) {
    int n = blockIdx.x, tid = threadIdx.x;
    finewait(&sF2[(n >> 5)*32], base, ep);
    float2* cs = (float2*)SMB;
    for (int idx = tid; idx < 32*C; idx += 256) {
        int b = idx / C, c = idx - b*C;
        float cv, sv;
        if (L == 0) {
            if (c == 0) { cv = src[((long)b*T_+t)*N_ + n]; sv = SCRATCH[OFF_AX + (long)n*384 + t*32 + b]; }
            else {
                int j = c-1;
                cv = SCRATCH[OFF_ZR + ((long)n*32+b)*128 + j] * SCRATCH[hRead + ((long)b*N_+n)*H_ + j];
                sv = SCRATCH[OFF_SPRZH + (long)n*2048 + b*64 + j];
            }
        } else {
            if (c < 64) { cv = SCRATCH[OFF_HS + (((long)b*T_+t)*N_+n)*H_ + c];
                          sv = SCRATCH[OFF_AHS + (long)n*24576 + t*2048 + b*64 + c]; }
            else {
                int j = c-64;
                cv = SCRATCH[OFF_ZR + ((long)n*32+b)*128 + j] * SCRATCH[hRead + ((long)b*N_+n)*H_ + j];
                sv = SCRATCH[OFF_SPRZH + (long)n*2048 + b*64 + j];
            }
        }
        cs[idx] = make_float2(cv, sv);
    }
    __syncthreads();
    int o = tid & 31, bg = tid >> 5;
    ull acc0[4], acc1[4];
    #pragma unroll
    for (int i=0;i<4;i++){acc0[i]=0ull;acc1[i]=0ull;}
    const float2* Wp = (const float2*)(SCRATCH + wOff + (long)n*(2*C*64));
    const float2* csb = cs + bg*4*C;
    int i = 0;
    for (; i + 8 <= C; i += 8) {
        ull wa[8], wb[8];
        #pragma unroll
        for (int j = 0; j < 8; j++) {
            wa[j] = *(const ull*)(Wp + (i+j)*64 + o);
            wb[j] = *(const ull*)(Wp + (i+j)*64 + o + 32);
        }
        #pragma unroll
        for (int j = 0; j < 8; j++) {
            #pragma unroll
            for (int bb = 0; bb < 4; bb++) {
                ull cp = *(const ull*)(csb + bb*C + i + j);
                asm("fma.rn.f32x2 %0, %1, %2, %0;" : "+l"(acc0[bb]) : "l"(cp), "l"(wa[j]));
                asm("fma.rn.f32x2 %0, %1, %2, %0;" : "+l"(acc1[bb]) : "l"(cp), "l"(wb[j]));
            }
        }
    }
    for (; i < C; i++) {
        ull wa = *(const ull*)(Wp + i*64 + o);
        ull wb = *(const ull*)(Wp + i*64 + o + 32);
        #pragma unroll
        for (int bb = 0; bb < 4; bb++) {
            ull cp = *(const ull*)(csb + bb*C + i);
            asm("fma.rn.f32x2 %0, %1, %2, %0;" : "+l"(acc0[bb]) : "l"(cp), "l"(wa));
            asm("fma.rn.f32x2 %0, %1, %2, %0;" : "+l"(acc1[bb]) : "l"(cp), "l"(wb));
        }
    }
    float bias0 = SCRATCH[bOff + (long)n*64 + o];
    float bias1 = SCRATCH[bOff + (long)n*64 + o + 32];
    #pragma unroll
    for (int bb = 0; bb < 4; bb++) {
        int b = bg*4 + bb;
        float2 a0 = *(float2*)&acc0[bb];
        float2 a1 = *(float2*)&acc1[bb];
        #pragma unroll
        for (int p = 0; p < 2; p++) {
            int oo = o + p*32;
            float hc = tanhf(p ? (a1.x+a1.y+bias1) : (a0.x+a0.y+bias0));
            float r  = SCRATCH[OFF_ZR + ((long)n*32 + b)*128 + 64 + oo];
            long hi = ((long)b*N_ + n)*H_ + oo;
            float hn = r*SCRATCH[hRead + hi] + (1.f - r)*hc;
            SCRATCH[hWrite + hi] = hn;
            if (writeHS) SCRATCH[OFF_HS + (((long)b*T_ + t)*N_ + n)*H_ + oo] = hn;
        }
    }
}

__device__ __forceinline__ void dZeroH(long off) {
    for (long i = (long)blockIdx.x*256 + threadIdx.x; i < HSZ; i += (long)NB*256)
        SCRATCH[off + i] = 0.f;
}

__global__ void __launch_bounds__(256, 3) kGRU(const float* __restrict__ src) {
    __shared__ __align__(16) char SMB[33280];
    __shared__ unsigned sBase[2];
    unsigned gen = 0;
    if (threadIdx.x == 0) {
        gen = atomicAdd(&gGen, 0);
        int rg = blockIdx.x >> 5;
        sBase[0] = sF1[rg*32];
        sBase[1] = sF2[rg*32];
    }

    int p = 0;   // h read-buffer parity
    int e1 = 0, e2 = 0;

    dSpread<0>(SMB, src, 0, OFF_AX, 384, nullptr);
    dZeroH(OFF_H);
    gbar(gen);
    unsigned b1 = sBase[0], b2 = sBase[1];

    for (int t = 0; t < T_; t++) {       // layer 0
        long hR = OFF_H + (long)p*HSZ, hW = OFF_H + (long)(p^1)*HSZ;
        dSpread<1>(SMB, src, hR, OFF_SPRH, 2048, sF1);
        e1++;
        dGate<65,0>(SMB, src, t, OFF_WG0, OFF_BG0, hR, b1, e1);
        gbar(gen);
        dSpread<2>(SMB, src, hR, OFF_SPRZH, 2048, sF2);
        e2++;
        dUpd<65,0>(SMB, src, t, OFF_WU0, OFF_BU0, hR, hW, 1, b2, e2);
        gbar(gen);
        p ^= 1;
    }

    dSpread<3>(SMB, src, 0, OFF_AHS, 24576, nullptr);
    dZeroH(OFF_H + (long)p*HSZ);
    gbar(gen);

    for (int t = 0; t < T_; t++) {       // layer 1
        long hR = OFF_H + (long)p*HSZ, hW = OFF_H + (long)(p^1)*HSZ;
        dSpread<1>(SMB, src, hR, OFF_SPRH, 2048, sF1);
        e1++;
        dGate<128,1>(SMB, src, t, OFF_WG1, OFF_BG1, hR, b1, e1);
        gbar(gen);
        dSpread<2>(SMB, src, hR, OFF_SPRZH, 2048, sF2);
        e2++;
        dUpd<128,1>(SMB, src, t, OFF_WU1, OFF_BU1, hR, hW, 0, b2, e2);
        gbar(gen);
        p ^= 1;
    }
    // after 24 flips p == 0; final h resides in buffer 0 (read by kOut)
}

// ---------------- transformer branch ----------------
__global__ void __launch_bounds__(256) kKV(const float* __restrict__ src,
        const float* __restrict__ mw, const float* __restrict__ mb,
        const float* __restrict__ wk, const float* __restrict__ bk,
        const float* __restrict__ wv, const float* __restrict__ bv) {
    __shared__ float xbT[64][64];
    __shared__ float wks[64][64];
    __shared__ float wvs[64][64];
    int tid = threadIdx.x, blk = blockIdx.x;

    if (tid < 64) {
        int row = blk*64 + tid;
        int t = row % 12, s = row / 12;
        int n = s % N_, b = s / N_;
        wks[0][tid] = src[((long)b*T_ + t)*N_ + n];
    }
    __syncthreads();
    for (int e = tid; e < 4096; e += 256) {
        int r = e >> 6, h = e & 63;
        int t = (blk*64 + r) % 12;
        xbT[h][r] = wks[0][r]*mw[h] + mb[h] + SCRATCH[OFF_PE + t*64 + h];
    }
    __syncthreads();
    for (int e = tid; e < 4096; e += 256) {
        wks[e >> 6][e & 63] = wk[e];
        wvs[e >> 6][e & 63] = wv[e];
    }
    __syncthreads();

    int col = tid & 63, rg = tid >> 6;
    ull accK[8], accV[8];
    #pragma unroll
    for (int i=0;i<8;i++){accK[i]=0ull;accV[i]=0ull;}
    #pragma unroll 4
    for (int kk = 0; kk < 64; kk++) {
        float a = wks[kk][col], b = wvs[kk][col];
        ull w1, w2;
        asm("mov.b64 %0, {%1, %1};" : "=l"(w1) : "f"(a));
        asm("mov.b64 %0, {%1, %1};" : "=l"(w2) : "f"(b));
        const ull* xp = (const ull*)&xbT[kk][rg*16];
        #pragma unroll
        for (int i=0;i<8;i++) {
            ull x = xp[i];
            asm("fma.rn.f32x2 %0, %1, %2, %0;" : "+l"(accK[i]) : "l"(x), "l"(w1));
            asm("fma.rn.f32x2 %0, %1, %2, %0;" : "+l"(accV[i]) : "l"(x), "l"(w2));
        }
    }
    float bkc = bk[col], bvc = bv[col];
    #pragma unroll
    for (int i=0;i<8;i++) {
        float2 k2 = *(float2*)&accK[i];
        float2 v2 = *(float2*)&accV[i];
        long r0 = ((long)blk*64 + rg*16 + 2*i)*64 + col;
        SCRATCH[OFF_K + r0]      = k2.x + bkc;
        SCRATCH[OFF_K + r0 + 64] = k2.y + bkc;
        SCRATCH[OFF_V + r0]      = v2.x + bvc;
        SCRATCH[OFF_V + r0 + 64] = v2.y + bvc;
    }
    for (int e = tid; e < 4096; e += 256) {
        int r = e >> 6, h = e & 63;
        int row = blk*64 + r;
        if (row % 12 == 11)
            SCRATCH[OFF_XB11 + (long)(row/12)*64 + h] = xbT[h][r];
    }
}

template<int NT>
__global__ void __launch_bounds__(256) kMM(long aOff, int lda,
        const float* __restrict__ Bx, int ldb,
        long cOff, int ldc, const float* __restrict__ bias,
        long resOff, int ldres, int hasRes,
        int M, int K, int Nc, int relu) {
    const int P = NT/32;
    const float* A = SCRATCH + aOff;
    float* Cm = SCRATCH + cOff;
    __shared__ float As[64][16];
    __shared__ float Bs[16][NT+2];
    int tx = threadIdx.x & 15, ty = threadIdx.x >> 4;
    int row0 = blockIdx.y*64, col0 = blockIdx.x*NT;
    ull acc[4][P];
    #pragma unroll
    for (int i=0;i<4;i++)
        #pragma unroll
        for (int p=0;p<P;p++) acc[i][p] = 0ull;
    for (int k0 = 0; k0 < K; k0 += 16) {
        for (int e = threadIdx.x; e < 64*16; e += 256) {
            int r = e >> 4, c = e & 15, gr = row0 + r, gc = k0 + c;
            As[r][c] = (gr < M && gc < K) ? A[(long)gr*lda + gc] : 0.f;
        }
        for (int e = threadIdx.x; e < 16*NT; e += 256) {
            int r = e / NT, c = e - (e/NT)*NT;
            int gr = k0 + r, gc = col0 + c;
            Bs[r][c] = (gr < K && gc < Nc) ? Bx[(long)gr*ldb + gc] : 0.f;
        }
        __syncthreads();
        #pragma unroll
        for (int kk = 0; kk < 16; kk++) {
            ull bv[P];
            #pragma unroll
            for (int p=0;p<P;p++) bv[p] = *(const ull*)&Bs[kk][32*p + 2*tx];
            #pragma unroll
            for (int i=0;i<4;i++) {
                float a = As[ty + 16*i][kk];
                ull aa;
                asm("mov.b64 %0, {%1, %1};" : "=l"(aa) : "f"(a));
                #pragma unroll
                for (int p=0;p<P;p++)
                    asm("fma.rn.f32x2 %0, %1, %2, %0;" : "+l"(acc[i][p]) : "l"(aa), "l"(bv[p]));
            }
        }
        __syncthreads();
    }
    #pragma unroll
    for (int i=0;i<4;i++) {
        int rr = row0 + ty + 16*i;
        if (rr >= M) continue;
        #pragma unroll
        for (int p=0;p<P;p++) {
            float2 v = *(float2*)&acc[i][p];
            int cc = col0 + 32*p + 2*tx;
            #pragma unroll
            for (int q=0;q<2;q++) {
                int c2 = cc + q;
                if (c2 >= Nc) continue;
                float val = q ? v.y : v.x;
                if (bias)   val += bias[c2];
                if (hasRes) val += SCRATCH[resOff + (long)rr*ldres + c2];
                if (relu)   val = fmaxf(val, 0.f);
                Cm[(long)rr*ldc + c2] = val;
            }
        }
    }
}

__global__ void kAttn() {
    int s = blockIdx.x, tid = threadIdx.x;
    int w = tid >> 5, lane = tid & 31;
    __shared__ float qs[64];
    __shared__ float att[4][12];
    if (tid < 64) qs[tid] = SCRATCH[OFF_Q + (long)s*64 + tid];
    __syncthreads();
    if (lane < 12) {
        float sc = 0.f;
        #pragma unroll
        for (int d = 0; d < 16; d++)
            sc += qs[w*16+d] * SCRATCH[OFF_K + (long)s*768 + lane*64 + w*16 + d];
        att[w][lane] = sc * 0.25f;
    }
    __syncwarp();
    float loc[12], mx = -1e30f, sum = 0.f;
    #pragma unroll
    for (int t = 0; t < 12; t++) { loc[t] = att[w][t]; mx = fmaxf(mx, loc[t]); }
    #pragma unroll
    for (int t = 0; t < 12; t++) { loc[t] = expf(loc[t]-mx); sum += loc[t]; }
    float inv = 1.f/sum;
    __syncwarp();
    if (lane < 16) {
        float acc = 0.f;
        #pragma unroll
        for (int t = 0; t < 12; t++)
            acc += loc[t]*inv * SCRATCH[OFF_V + (long)s*768 + t*64 + w*16 + lane];
        SCRATCH[OFF_OB + (long)s*64 + w*16 + lane] = acc;
    }
}

__global__ void kLN(long inOff, long outOff, const float* __restrict__ g, const float* __restrict__ b) {
    int row = blockIdx.x, tid = threadIdx.x;
    __shared__ float red[64];
    float v = SCRATCH[inOff + (long)row*64 + tid];
    red[tid] = v; __syncthreads();
    for (int s = 32; s > 0; s >>= 1) { if (tid < s) red[tid] += red[tid+s]; __syncthreads(); }
    float m = red[0]/64.f; __syncthreads();
    float d = v - m;
    red[tid] = d*d; __syncthreads();
    for (int s = 32; s > 0; s >>= 1) { if (tid < s) red[tid] += red[tid+s]; __syncthreads(); }
    float var = red[0]/64.f;
    SCRATCH[outOff + (long)row*64 + tid] = d*rsqrtf(var + 1e-5f)*g[tid] + b[tid];
}

__global__ void kOut(float* __restrict__ out, const float* __restrict__ ws, const float* __restrict__ wt,
                     const float* __restrict__ cw, const float* __restrict__ cb) {
    int s = blockIdx.x, tid = threadIdx.x;
    int n = s % N_, b = s / N_;
    __shared__ float comb[64];
    comb[tid] = SCRATCH[OFF_H + (long)s*64 + tid]*ws[n*64+tid]
              + SCRATCH[OFF_OB + (long)s*64 + tid]*wt[n*64+tid];
    __syncthreads();
    if (tid < 12) {
        float acc = cb[tid];
        #pragma unroll
        for (int h = 0; h < 64; h++) acc += comb[h]*cw[tid*64+h];
        out[((long)b*12 + tid)*N_ + n] = acc;
    }
}

extern "C" void kernel_launch(void* const* d_in, const int* in_sizes, int n_in,
                              void* d_out, int out_size) {
    const float* source  = (const float*)d_in[0];
    const float* emb     = (const float*)d_in[1];
    const float* gate_w0 = (const float*)d_in[2];
    const float* gate_b0 = (const float*)d_in[3];
    const float* upd_w0  = (const float*)d_in[4];
    const float* upd_b0  = (const float*)d_in[5];
    const float* gate_w1 = (const float*)d_in[6];
    const float* gate_b1 = (const float*)d_in[7];
    const float* upd_w1  = (const float*)d_in[8];
    const float* upd_b1  = (const float*)d_in[9];
    const float* mlp_w   = (const float*)d_in[10];
    const float* mlp_b   = (const float*)d_in[11];
    const float* wq = (const float*)d_in[12];  const float* bq = (const float*)d_in[13];
    const float* wk = (const float*)d_in[14];  const float* bk = (const float*)d_in[15];
    const float* wv = (const float*)d_in[16];  const float* bv = (const float*)d_in[17];
    const float* wo = (const float*)d_in[18];  const float* bo = (const float*)d_in[19];
    const float* fw1 = (const float*)d_in[20]; const float* fb1 = (const float*)d_in[21];
    const float* fw2 = (const float*)d_in[22]; const float* fb2 = (const float*)d_in[23];
    const float* l1g = (const float*)d_in[24]; const float* l1b = (const float*)d_in[25];
    const float* l2g = (const float*)d_in[26]; const float* l2b = (const float*)d_in[27];
    const float* ws  = (const float*)d_in[28]; const float* wt  = (const float*)d_in[29];
    const float* cw  = (const float*)d_in[30]; const float* cb  = (const float*)d_in[31];
    float* out = (float*)d_out;

    kA<<<N_, 256>>>(emb);
    kMixAll<<<dim3(292, N_), 256>>>(gate_w0, upd_w0, gate_w1, upd_w1,
                                    gate_b0, upd_b0, gate_b1, upd_b1, emb);
    kKV<<<1842, 256>>>(source, mlp_w, mlp_b, wk, bk, wv, bv);

    kGRU<<<NB, 256>>>(source);

    kMM<64><<<dim3(1,154),256>>>(OFF_XB11,64, wq,64, OFF_Q,64, bq, 0,0,0, 9824,64,64,0);
    kAttn<<<9824,128>>>();
    kMM<64><<<dim3(1,154),256>>>(OFF_OB,64, wo,64, OFF_Q,64, bo, OFF_XB11,64,1, 9824,64,64,0);
    kLN<<<9824,64>>>(OFF_Q, OFF_LN1, l1g, l1b);
    kMM<128><<<dim3(8,154),256>>>(OFF_LN1,64, fw1,1024, OFF_F1,1024, fb1, 0,0,0, 9824,64,1024,1);
    kMM<64><<<dim3(1,154),256>>>(OFF_F1,1024, fw2,64, OFF_F2,64, fb2, OFF_LN1,64,1, 9824,1024,64,0);
    kLN<<<9824,64>>>(OFF_F2, OFF_OB, l2g, l2b);

    kOut<<<9824,64>>>(out, ws, wt, cw, cb);
}